// round 15
// baseline (speedup 1.0000x reference)
#include <cuda_runtime.h>
#include <cuda_fp16.h>
#include <cstdint>

#define S_LEN 2176
#define NQH 32
#define NKVH 8
#define HD 128
#define WIN 256
#define NMETA 128
#define BM 64
#define BN 64
#define SCALE 0.08838834764831845f
#define LOG2E 1.4426950408889634f

// smem strides (bytes): 128 fp16 + 16B pad -> conflict-free ldmatrix
#define QSTR 272
#define VSTR 144
#define Q_SZ (BM * QSTR)
#define K_SZ (BN * QSTR)
#define V_SZ (HD * VSTR)
#define OFF_Q 0
#define OFF_K (Q_SZ)
#define OFF_V (Q_SZ + 2 * K_SZ)
#define SMEM_TOTAL (OFF_V + V_SZ)  // 70656 B -> occupancy 3

#define ROPE_BLOCKS S_LEN
#define VT_SBLK (S_LEN / 64)
#define VT_DBLK (HD / 32)
#define VT_BLOCKS (VT_SBLK * VT_DBLK * NKVH)

__device__ __align__(16) __half g_k[NKVH * S_LEN * HD];
__device__ __align__(16) __half g_vt[NKVH * HD * S_LEN];
__device__ __align__(16) float2 g_cs[S_LEN * 64];  // (cos, sin) per (s, j)

typedef unsigned long long u64;

__device__ __forceinline__ uint32_t smem_u32(const void* p) {
    uint32_t a;
    asm("{ .reg .u64 t; cvta.to.shared.u64 t, %1; cvt.u32.u64 %0, t; }" : "=r"(a) : "l"(p));
    return a;
}

#define LDSM4(r0, r1, r2, r3, a)                                                 \
    asm volatile("ldmatrix.sync.aligned.m8n8.x4.shared.b16 {%0,%1,%2,%3}, [%4];" \
                 : "=r"(r0), "=r"(r1), "=r"(r2), "=r"(r3) : "r"(a))

#define MMA4(c, a, b0, b1)                                                   \
    asm volatile(                                                            \
        "mma.sync.aligned.m16n8k16.row.col.f32.f16.f16.f32 "                 \
        "{%0,%1,%2,%3},{%4,%5,%6,%7},{%8,%9},{%0,%1,%2,%3};"                 \
        : "+f"((c)[0]), "+f"((c)[1]), "+f"((c)[2]), "+f"((c)[3])             \
        : "r"((a)[0]), "r"((a)[1]), "r"((a)[2]), "r"((a)[3]), "r"(b0), "r"(b1))

#define CPA16(d, s) \
    asm volatile("cp.async.cg.shared.global [%0], [%1], 16;" ::"r"(d), "l"(s))
#define CPA_COMMIT() asm volatile("cp.async.commit_group;" ::: "memory")
#define CPA_WAIT2() asm volatile("cp.async.wait_group 2;" ::: "memory")
#define CPA_WAIT1() asm volatile("cp.async.wait_group 1;" ::: "memory")
#define CPA_WAIT0() asm volatile("cp.async.wait_group 0;" ::: "memory")

// ---- packed f32x2 helpers ----
__device__ __forceinline__ u64 add2(u64 a, u64 b) {
    u64 d;
    asm("add.rn.f32x2 %0, %1, %2;" : "=l"(d) : "l"(a), "l"(b));
    return d;
}
__device__ __forceinline__ u64 fma2(u64 a, u64 b, u64 c) {
    u64 d;
    asm("fma.rn.f32x2 %0, %1, %2, %3;" : "=l"(d) : "l"(a), "l"(b), "l"(c));
    return d;
}
__device__ __forceinline__ u64 pk2(float x, float y) {
    u64 r;
    asm("mov.b64 %0, {%1, %2};" : "=l"(r) : "f"(x), "f"(y));
    return r;
}
__device__ __forceinline__ float2 upk2(u64 v) {
    float2 r;
    asm("mov.b64 {%0, %1}, %2;" : "=f"(r.x), "=f"(r.y) : "l"(v));
    return r;
}
#define PK2C(f) ((((u64)__float_as_uint(f)) << 32) | (u64)__float_as_uint(f))

// packed exp2 via magic-constant range reduction; deg-4 poly; exponent
// injected by per-lane (y_bits << 23) add.
__device__ __forceinline__ u64 fexp2x2(u64 t) {
    const u64 C2 = PK2C(12582912.0f);
    u64 y = add2(t, C2);
    u64 g = add2(t, fma2(y, PK2C(-1.0f), C2));  // t - (y - C)
    u64 p = fma2(g, PK2C(0.00961812f), PK2C(0.0555041f));
    p = fma2(p, g, PK2C(0.240227f));
    p = fma2(p, g, PK2C(0.693147f));
    p = fma2(p, g, PK2C(1.0f));
    uint32_t ylo = (uint32_t)y, yhi = (uint32_t)(y >> 32);
    uint32_t plo = (uint32_t)p, phi = (uint32_t)(p >> 32);
    plo += ylo << 23;
    phi += yhi << 23;
    return ((u64)phi << 32) | (u64)plo;
}

// ---------------- fused prep: K RoPE + cos/sin table | V transpose ------------
__global__ void prep_kernel(const float* __restrict__ k_in, const float* __restrict__ v_in) {
    const int tid = threadIdx.x;
    if (blockIdx.x < ROPE_BLOCKS) {
        __shared__ float s_cos[64], s_sin[64];
        const int s = blockIdx.x;
        if (tid < 64) {
            float inv = exp2f((float)tid * (-13.287712379549449f / 64.0f));
            float th = (float)s * inv;
            float sn, c;
            sincosf(th, &sn, &c);
            s_sin[tid] = sn;
            s_cos[tid] = c;
            g_cs[s * 64 + tid] = make_float2(c, sn);
        }
        __syncthreads();
#pragma unroll
        for (int i = 0; i < 2; ++i) {
            int p = tid + i * 256;  // 512 (kh, j) pairs
            int kh = p >> 6, j = p & 63;
            const float c = s_cos[j], sn = s_sin[j];
            const float* src = k_in + ((size_t)s * NKVH + kh) * HD;
            float a = src[j], b = src[j + 64];
            size_t o = ((size_t)kh * S_LEN + s) * HD;
            g_k[o + j] = __float2half_rn(a * c - b * sn);
            g_k[o + j + 64] = __float2half_rn(b * c + a * sn);
        }
    } else {
        __shared__ float t[64][33];
        int bx = blockIdx.x - ROPE_BLOCKS;
        const int kh = bx / (VT_SBLK * VT_DBLK);
        int rem = bx % (VT_SBLK * VT_DBLK);
        const int s_base = (rem % VT_SBLK) * 64;
        const int d_base = (rem / VT_SBLK) * 32;
#pragma unroll
        for (int i = 0; i < 8; ++i) {
            int idx = tid + i * 256;
            int r = idx >> 5, c = idx & 31;
            t[r][c] = v_in[(size_t)(s_base + r) * (NKVH * HD) + kh * HD + d_base + c];
        }
        __syncthreads();
#pragma unroll
        for (int i = 0; i < 4; ++i) {
            int idx = tid + i * 256;
            int d = idx >> 5, sp = idx & 31;
            __half2 h = __floats2half2_rn(t[2 * sp][d], t[2 * sp + 1][d]);
            *(__half2*)(g_vt + (size_t)(kh * HD + d_base + d) * S_LEN + s_base + 2 * sp) = h;
        }
    }
}

// ---------------- attention: software-pipelined fp16 HMMA flash attention -----
__global__ void __launch_bounds__(128, 3)
attn_kernel(const float* __restrict__ q_in, float* __restrict__ out) {
    extern __shared__ char smem[];
    const uint32_t sb = smem_u32(smem);
    const int tid = threadIdx.x;
    const int lane = tid & 31, w = tid >> 5;
    const int h = blockIdx.y, kh = h >> 2;
    // LPT: heavy (large-q0) blocks first so the tail wave holds light ones
    const int q0 = ((int)gridDim.x - 1 - (int)blockIdx.x) * BM;

    // tile list: meta prefix then sliding window; the LAST tile is always the
    // diagonal (kv0 == q0), where column-tiles np > w are fully causal-masked
    // for warp w.
    int kvs[8];
    int ntl = 0;
    int pend = NMETA < q0 + BM ? NMETA : q0 + BM;
    for (int kv = 0; kv < pend; kv += BN) kvs[ntl++] = kv;
    int wbeg = q0 - WIN;
    if (wbeg < NMETA) wbeg = NMETA;
    for (int kv = wbeg; kv < q0 + BM; kv += BN) kvs[ntl++] = kv;

    auto load_K = [&](int kv0, int buf) {
        const __half* kg = g_k + (((size_t)kh * S_LEN + kv0) << 7);
#pragma unroll
        for (int it = 0; it < 8; ++it) {
            int idx = tid + it * 128;
            int r = idx >> 4, c = idx & 15;
            CPA16(sb + OFF_K + buf * K_SZ + r * QSTR + c * 16, kg + ((size_t)r << 7) + c * 8);
        }
    };
    auto load_V = [&](int kv0) {
        const __half* vg = g_vt + (size_t)kh * HD * S_LEN + kv0;
#pragma unroll
        for (int it = 0; it < 8; ++it) {
            int idx = tid + it * 128;
            int r = idx >> 3, c = idx & 7;
            CPA16(sb + OFF_V + r * VSTR + c * 16, vg + (size_t)r * S_LEN + c * 8);
        }
    };

    // prologue: K0 | V0 | K1 (empty commit if absent)
    load_K(kvs[0], 0);
    CPA_COMMIT();
    load_V(kvs[0]);
    CPA_COMMIT();
    if (ntl > 1) load_K(kvs[1], 1);
    CPA_COMMIT();

    // Q-RoPE + scale + fp16 -> smem. 1024 items = 64 rows x 16 j-groups.
    {
        const float* qg = q_in + (size_t)q0 * (NQH * HD) + h * HD;
        const float* cs = (const float*)(g_cs + (size_t)q0 * 64);
#pragma unroll
        for (int i = 0; i < 8; ++i) {
            int item = tid + i * 128;
            int r = item >> 4, cq = item & 15;
            const float* row = qg + (size_t)r * (NQH * HD);
            float4 a = *(const float4*)(row + cq * 4);
            float4 b = *(const float4*)(row + 64 + cq * 4);
            float4 c0 = *(const float4*)(cs + r * 128 + cq * 8);
            float4 c1 = *(const float4*)(cs + r * 128 + cq * 8 + 4);
            const float sc = SCALE * LOG2E;
            float x0 = (a.x * c0.x - b.x * c0.y) * sc, y0 = (b.x * c0.x + a.x * c0.y) * sc;
            float x1 = (a.y * c0.z - b.y * c0.w) * sc, y1 = (b.y * c0.z + a.y * c0.w) * sc;
            float x2 = (a.z * c1.x - b.z * c1.y) * sc, y2 = (b.z * c1.x + a.z * c1.y) * sc;
            float x3 = (a.w * c1.z - b.w * c1.w) * sc, y3 = (b.w * c1.z + a.w * c1.w) * sc;
            __half2 hx01 = __floats2half2_rn(x0, x1), hx23 = __floats2half2_rn(x2, x3);
            __half2 hy01 = __floats2half2_rn(y0, y1), hy23 = __floats2half2_rn(y2, y3);
            char* base = smem + OFF_Q + r * QSTR + cq * 8;
            *(uint2*)base = make_uint2(*(uint32_t*)&hx01, *(uint32_t*)&hx23);
            *(uint2*)(base + 128) = make_uint2(*(uint32_t*)&hy01, *(uint32_t*)&hy23);
        }
    }

    const uint32_t qa = sb + OFF_Q + (w * 16 + (lane & 15)) * QSTR + (lane >> 4) * 16;
    const int brow = (lane & 7) + ((lane >> 4) << 3);
    const int qi = q0 + w * 16 + (lane >> 2);
    const int jc = 2 * (lane & 3);

    float o[16][4];
#pragma unroll
    for (int nt = 0; nt < 16; ++nt)
#pragma unroll
        for (int e = 0; e < 4; ++e) o[nt][e] = 0.f;
    u64 ls0v = 0ull, ls1v = 0ull;

    const uint32_t va = sb + OFF_V + brow * VSTR + (lane & 8) * 2;
    float sacc[8][4];

    // ---- S(0) ----
    CPA_WAIT2();  // K0 ready (V0, K1 may pend)
    __syncthreads();
    {
        // if the first tile is ALSO the diagonal (ntl==1), skip np > w
        const int npmax0 = (ntl == 1) ? (w + 1) : 4;
        const uint32_t ka = sb + OFF_K + brow * QSTR + (lane & 8) * 2;
#pragma unroll
        for (int ct = 0; ct < 8; ++ct)
#pragma unroll
            for (int e = 0; e < 4; ++e) sacc[ct][e] = 0.f;
#pragma unroll
        for (int ks = 0; ks < 8; ++ks) {
            uint32_t qf[4];
            LDSM4(qf[0], qf[1], qf[2], qf[3], qa + ks * 32);
#pragma unroll
            for (int np = 0; np < 4; ++np) {
                if (np < npmax0) {
                    uint32_t kb[4];
                    LDSM4(kb[0], kb[1], kb[2], kb[3], ka + np * (16 * QSTR) + ks * 32);
                    MMA4(sacc[2 * np], qf, kb[0], kb[1]);
                    MMA4(sacc[2 * np + 1], qf, kb[2], kb[3]);
                }
            }
        }
    }

    for (int t = 0; t < ntl; ++t) {
        const int kv0 = kvs[t];

        // ---- softmax(t): p = 2^s (packed f32x2), mask only boundary tiles ----
        const bool full = (kv0 + BN <= q0 + 1) &&
                          ((kv0 >= q0 - WIN + BN - 1) || (kv0 + BN <= NMETA));
        uint32_t ph[4][4];
        if (full) {
#pragma unroll
            for (int ct = 0; ct < 8; ++ct) {
                u64 p01 = fexp2x2(pk2(sacc[ct][0], sacc[ct][1]));
                u64 p23 = fexp2x2(pk2(sacc[ct][2], sacc[ct][3]));
                ls0v = add2(ls0v, p01);
                ls1v = add2(ls1v, p23);
                float2 f01 = upk2(p01), f23 = upk2(p23);
                __half2 h01 = __floats2half2_rn(f01.x, f01.y);
                __half2 h23 = __floats2half2_rn(f23.x, f23.y);
                ph[ct >> 1][(ct & 1) * 2] = *(uint32_t*)&h01;
                ph[ct >> 1][(ct & 1) * 2 + 1] = *(uint32_t*)&h23;
            }
        } else {
#pragma unroll
            for (int ct = 0; ct < 8; ++ct) {
                int j0 = kv0 + ct * 8 + jc;
                float s[4];
#pragma unroll
                for (int e = 0; e < 4; ++e) {
                    int j = j0 + (e & 1);
                    int qr = qi + (e >> 1) * 8;
                    bool ok = (j <= qr) && ((qr - j) <= WIN || j < NMETA);
                    s[e] = ok ? sacc[ct][e] : -126.0f;
                }
                u64 p01 = fexp2x2(pk2(s[0], s[1]));
                u64 p23 = fexp2x2(pk2(s[2], s[3]));
                ls0v = add2(ls0v, p01);
                ls1v = add2(ls1v, p23);
                float2 f01 = upk2(p01), f23 = upk2(p23);
                __half2 h01 = __floats2half2_rn(f01.x, f01.y);
                __half2 h23 = __floats2half2_rn(f23.x, f23.y);
                ph[ct >> 1][(ct & 1) * 2] = *(uint32_t*)&h01;
                ph[ct >> 1][(ct & 1) * 2 + 1] = *(uint32_t*)&h23;
            }
        }

        // V(t) and (if any) K(t+1) ready
        CPA_WAIT0();
        __syncthreads();

        if (t + 1 < ntl) {
            // ---- fused: PV(t) + S(t+1), two independent LDSM/MMA streams ----
            // if t+1 is the diagonal tile, skip its column-tiles np > w
            const int npmax = (t + 2 == ntl) ? (w + 1) : 4;
            const uint32_t ka = sb + OFF_K + ((t + 1) & 1) * K_SZ + brow * QSTR + (lane & 8) * 2;
#pragma unroll
            for (int ct = 0; ct < 8; ++ct)
#pragma unroll
                for (int e = 0; e < 4; ++e) sacc[ct][e] = 0.f;
#pragma unroll
            for (int st = 0; st < 8; ++st) {
                // S(t+1), k-step st
                uint32_t qf[4];
                LDSM4(qf[0], qf[1], qf[2], qf[3], qa + st * 32);
#pragma unroll
                for (int np = 0; np < 4; ++np) {
                    if (np < npmax) {
                        uint32_t kb[4];
                        LDSM4(kb[0], kb[1], kb[2], kb[3], ka + np * (16 * QSTR) + st * 32);
                        MMA4(sacc[2 * np], qf, kb[0], kb[1]);
                        MMA4(sacc[2 * np + 1], qf, kb[2], kb[3]);
                    }
                }
                // PV(t), quarter st: kk = st>>1, ntp in [ (st&1)*4, +4 )
                const int kk = st >> 1;
#pragma unroll
                for (int j = 0; j < 4; ++j) {
                    const int ntp = (st & 1) * 4 + j;
                    uint32_t vb[4];
                    LDSM4(vb[0], vb[1], vb[2], vb[3], va + ntp * (16 * VSTR) + kk * 32);
                    MMA4(o[2 * ntp], ph[kk], vb[0], vb[1]);
                    MMA4(o[2 * ntp + 1], ph[kk], vb[2], vb[3]);
                }
            }
        } else {
            // ---- final tile: PV only. This is the diagonal tile: P columns
            // kk > w are all-zero for warp w -> skip those LDSM+MMA groups.
#pragma unroll
            for (int kk = 0; kk < 4; ++kk) {
                if (kk <= w) {
#pragma unroll
                    for (int ntp = 0; ntp < 8; ++ntp) {
                        uint32_t vb[4];
                        LDSM4(vb[0], vb[1], vb[2], vb[3], va + ntp * (16 * VSTR) + kk * 32);
                        MMA4(o[2 * ntp], ph[kk], vb[0], vb[1]);
                        MMA4(o[2 * ntp + 1], ph[kk], vb[2], vb[3]);
                    }
                }
            }
        }
        __syncthreads();

        // issue V(t+1) then K(t+2); empty commits keep wait counts uniform
        if (t + 1 < ntl) load_V(kvs[t + 1]);
        CPA_COMMIT();
        if (t + 2 < ntl) load_K(kvs[t + 2], t & 1);
        CPA_COMMIT();
    }

    // ---- epilogue: quad row-sum reduce, normalize, store ----
    float2 l0 = upk2(ls0v), l1 = upk2(ls1v);
    float ls0 = l0.x + l0.y, ls1 = l1.x + l1.y;
    ls0 += __shfl_xor_sync(0xffffffffu, ls0, 1);
    ls0 += __shfl_xor_sync(0xffffffffu, ls0, 2);
    ls1 += __shfl_xor_sync(0xffffffffu, ls1, 1);
    ls1 += __shfl_xor_sync(0xffffffffu, ls1, 2);
    float inv0 = 1.0f / ls0, inv1 = 1.0f / ls1;
    float* ob0 = out + (size_t)qi * (NQH * HD) + h * HD + jc;
    float* ob1 = out + (size_t)(qi + 8) * (NQH * HD) + h * HD + jc;
#pragma unroll
    for (int nt = 0; nt < 16; ++nt) {
        *(float2*)(ob0 + nt * 8) = make_float2(o[nt][0] * inv0, o[nt][1] * inv0);
        *(float2*)(ob1 + nt * 8) = make_float2(o[nt][2] * inv1, o[nt][3] * inv1);
    }
}

extern "C" void kernel_launch(void* const* d_in, const int* in_sizes, int n_in,
                              void* d_out, int out_size) {
    const float* q = (const float*)d_in[0];
    const float* k = (const float*)d_in[1];
    const float* v = (const float*)d_in[2];
    float* out = (float*)d_out;

    prep_kernel<<<ROPE_BLOCKS + VT_BLOCKS, 256>>>(k, v);

    cudaFuncSetAttribute(attn_kernel, cudaFuncAttributeMaxDynamicSharedMemorySize, SMEM_TOTAL);
    attn_kernel<<<dim3(S_LEN / BM, NQH), 128, SMEM_TOTAL>>>(q, out);
}

// round 16
// speedup vs baseline: 1.0586x; 1.0586x over previous
#include <cuda_runtime.h>
#include <cuda_fp16.h>
#include <cstdint>

#define S_LEN 2176
#define NQH 32
#define NKVH 8
#define HD 128
#define WIN 256
#define NMETA 128
#define BM 64
#define BN 64
#define SCALE 0.08838834764831845f
#define LOG2E 1.4426950408889634f

// smem strides (bytes): 128 fp16 + 16B pad -> conflict-free ldmatrix
#define QSTR 272
#define VSTR 144
#define K_SZ (BN * QSTR)
#define V_SZ (HD * VSTR)
#define OFF_K0 0
#define OFF_K1 (K_SZ)
#define OFF_V0 (2 * K_SZ)
#define OFF_V1 (2 * K_SZ + V_SZ)
#define SMEM_TOTAL (2 * K_SZ + 2 * V_SZ)  // 71680 B -> occupancy 3

#define ROPE_BLOCKS S_LEN
#define VT_SBLK (S_LEN / 64)
#define VT_DBLK (HD / 32)
#define VT_BLOCKS (VT_SBLK * VT_DBLK * NKVH)

__device__ __align__(16) __half g_k[NKVH * S_LEN * HD];
__device__ __align__(16) __half g_vt[NKVH * HD * S_LEN];
__device__ __align__(16) float2 g_cs[S_LEN * 64];  // (cos, sin) per (s, j)

typedef unsigned long long u64;

__device__ __forceinline__ uint32_t smem_u32(const void* p) {
    uint32_t a;
    asm("{ .reg .u64 t; cvta.to.shared.u64 t, %1; cvt.u32.u64 %0, t; }" : "=r"(a) : "l"(p));
    return a;
}

#define LDSM4(r0, r1, r2, r3, a)                                                 \
    asm volatile("ldmatrix.sync.aligned.m8n8.x4.shared.b16 {%0,%1,%2,%3}, [%4];" \
                 : "=r"(r0), "=r"(r1), "=r"(r2), "=r"(r3) : "r"(a))

#define MMA4(c, a, b0, b1)                                                   \
    asm volatile(                                                            \
        "mma.sync.aligned.m16n8k16.row.col.f32.f16.f16.f32 "                 \
        "{%0,%1,%2,%3},{%4,%5,%6,%7},{%8,%9},{%0,%1,%2,%3};"                 \
        : "+f"((c)[0]), "+f"((c)[1]), "+f"((c)[2]), "+f"((c)[3])             \
        : "r"((a)[0]), "r"((a)[1]), "r"((a)[2]), "r"((a)[3]), "r"(b0), "r"(b1))

#define CPA16(d, s) \
    asm volatile("cp.async.cg.shared.global [%0], [%1], 16;" ::"r"(d), "l"(s))
#define CPA_COMMIT() asm volatile("cp.async.commit_group;" ::: "memory")
#define CPA_WAIT3() asm volatile("cp.async.wait_group 3;" ::: "memory")

// ---- packed f32x2 helpers ----
__device__ __forceinline__ u64 add2(u64 a, u64 b) {
    u64 d;
    asm("add.rn.f32x2 %0, %1, %2;" : "=l"(d) : "l"(a), "l"(b));
    return d;
}
__device__ __forceinline__ u64 fma2(u64 a, u64 b, u64 c) {
    u64 d;
    asm("fma.rn.f32x2 %0, %1, %2, %3;" : "=l"(d) : "l"(a), "l"(b), "l"(c));
    return d;
}
__device__ __forceinline__ u64 pk2(float x, float y) {
    u64 r;
    asm("mov.b64 %0, {%1, %2};" : "=l"(r) : "f"(x), "f"(y));
    return r;
}
__device__ __forceinline__ float2 upk2(u64 v) {
    float2 r;
    asm("mov.b64 {%0, %1}, %2;" : "=f"(r.x), "=f"(r.y) : "l"(v));
    return r;
}
#define PK2C(f) ((((u64)__float_as_uint(f)) << 32) | (u64)__float_as_uint(f))

// packed exp2 via magic-constant range reduction; deg-4 poly; exponent
// injected by per-lane (y_bits << 23) add.
__device__ __forceinline__ u64 fexp2x2(u64 t) {
    const u64 C2 = PK2C(12582912.0f);
    u64 y = add2(t, C2);
    u64 g = add2(t, fma2(y, PK2C(-1.0f), C2));  // t - (y - C)
    u64 p = fma2(g, PK2C(0.00961812f), PK2C(0.0555041f));
    p = fma2(p, g, PK2C(0.240227f));
    p = fma2(p, g, PK2C(0.693147f));
    p = fma2(p, g, PK2C(1.0f));
    uint32_t ylo = (uint32_t)y, yhi = (uint32_t)(y >> 32);
    uint32_t plo = (uint32_t)p, phi = (uint32_t)(p >> 32);
    plo += ylo << 23;
    phi += yhi << 23;
    return ((u64)phi << 32) | (u64)plo;
}

// ---------------- fused prep: K RoPE + cos/sin table | V transpose ------------
__global__ void prep_kernel(const float* __restrict__ k_in, const float* __restrict__ v_in) {
    const int tid = threadIdx.x;
    if (blockIdx.x < ROPE_BLOCKS) {
        __shared__ float s_cos[64], s_sin[64];
        const int s = blockIdx.x;
        if (tid < 64) {
            float inv = exp2f((float)tid * (-13.287712379549449f / 64.0f));
            float th = (float)s * inv;
            float sn, c;
            sincosf(th, &sn, &c);
            s_sin[tid] = sn;
            s_cos[tid] = c;
            g_cs[s * 64 + tid] = make_float2(c, sn);
        }
        __syncthreads();
#pragma unroll
        for (int i = 0; i < 2; ++i) {
            int p = tid + i * 256;  // 512 (kh, j) pairs
            int kh = p >> 6, j = p & 63;
            const float c = s_cos[j], sn = s_sin[j];
            const float* src = k_in + ((size_t)s * NKVH + kh) * HD;
            float a = src[j], b = src[j + 64];
            size_t o = ((size_t)kh * S_LEN + s) * HD;
            g_k[o + j] = __float2half_rn(a * c - b * sn);
            g_k[o + j + 64] = __float2half_rn(b * c + a * sn);
        }
    } else {
        __shared__ float t[64][33];
        int bx = blockIdx.x - ROPE_BLOCKS;
        const int kh = bx / (VT_SBLK * VT_DBLK);
        int rem = bx % (VT_SBLK * VT_DBLK);
        const int s_base = (rem % VT_SBLK) * 64;
        const int d_base = (rem / VT_SBLK) * 32;
#pragma unroll
        for (int i = 0; i < 8; ++i) {
            int idx = tid + i * 256;
            int r = idx >> 5, c = idx & 31;
            t[r][c] = v_in[(size_t)(s_base + r) * (NKVH * HD) + kh * HD + d_base + c];
        }
        __syncthreads();
#pragma unroll
        for (int i = 0; i < 4; ++i) {
            int idx = tid + i * 256;
            int d = idx >> 5, sp = idx & 31;
            __half2 h = __floats2half2_rn(t[2 * sp][d], t[2 * sp + 1][d]);
            *(__half2*)(g_vt + (size_t)(kh * HD + d_base + d) * S_LEN + s_base + 2 * sp) = h;
        }
    }
}

// ------- attention: fp16 HMMA flash attention, Q in registers, K/V dbl-buf ----
__global__ void __launch_bounds__(128, 3)
attn_kernel(const float* __restrict__ q_in, float* __restrict__ out) {
    extern __shared__ char smem[];
    const uint32_t sb = smem_u32(smem);
    const int tid = threadIdx.x;
    const int lane = tid & 31, w = tid >> 5;
    const int h = blockIdx.y, kh = h >> 2;
    // LPT: heavy (large-q0) blocks first so the tail wave holds light ones
    const int q0 = ((int)gridDim.x - 1 - (int)blockIdx.x) * BM;

    // tile list: meta prefix then sliding window
    int kvs[7];
    int ntl = 0;
    int pend = NMETA < q0 + BM ? NMETA : q0 + BM;
    for (int kv = 0; kv < pend; kv += BN) kvs[ntl++] = kv;
    int wbeg = q0 - WIN;
    if (wbeg < NMETA) wbeg = NMETA;
    for (int kv = wbeg; kv < q0 + BM; kv += BN) kvs[ntl++] = kv;

    auto load_K = [&](int kv0, int buf) {
        const __half* kg = g_k + (((size_t)kh * S_LEN + kv0) << 7);
#pragma unroll
        for (int it = 0; it < 8; ++it) {
            int idx = tid + it * 128;
            int r = idx >> 4, c = idx & 15;
            CPA16(sb + OFF_K0 + buf * K_SZ + r * QSTR + c * 16, kg + ((size_t)r << 7) + c * 8);
        }
    };
    auto load_V = [&](int kv0, int buf) {
        const __half* vg = g_vt + (size_t)kh * HD * S_LEN + kv0;
#pragma unroll
        for (int it = 0; it < 8; ++it) {
            int idx = tid + it * 128;
            int r = idx >> 3, c = idx & 7;
            CPA16(sb + OFF_V0 + buf * V_SZ + r * VSTR + c * 16, vg + (size_t)r * S_LEN + c * 8);
        }
    };

    // ---- prologue A: Q-RoPE -> smem staging (K0 area), ldmatrix -> registers --
    {
        const float* qg = q_in + (size_t)q0 * (NQH * HD) + h * HD;
        const float* cs = (const float*)(g_cs + (size_t)q0 * 64);
#pragma unroll
        for (int i = 0; i < 8; ++i) {
            int item = tid + i * 128;
            int r = item >> 4, cq = item & 15;
            const float* row = qg + (size_t)r * (NQH * HD);
            float4 a = *(const float4*)(row + cq * 4);
            float4 b = *(const float4*)(row + 64 + cq * 4);
            float4 c0 = *(const float4*)(cs + r * 128 + cq * 8);
            float4 c1 = *(const float4*)(cs + r * 128 + cq * 8 + 4);
            const float sc = SCALE * LOG2E;
            float x0 = (a.x * c0.x - b.x * c0.y) * sc, y0 = (b.x * c0.x + a.x * c0.y) * sc;
            float x1 = (a.y * c0.z - b.y * c0.w) * sc, y1 = (b.y * c0.z + a.y * c0.w) * sc;
            float x2 = (a.z * c1.x - b.z * c1.y) * sc, y2 = (b.z * c1.x + a.z * c1.y) * sc;
            float x3 = (a.w * c1.z - b.w * c1.w) * sc, y3 = (b.w * c1.z + a.w * c1.w) * sc;
            __half2 hx01 = __floats2half2_rn(x0, x1), hx23 = __floats2half2_rn(x2, x3);
            __half2 hy01 = __floats2half2_rn(y0, y1), hy23 = __floats2half2_rn(y2, y3);
            char* base = smem + OFF_K0 + r * QSTR + cq * 8;
            *(uint2*)base = make_uint2(*(uint32_t*)&hx01, *(uint32_t*)&hx23);
            *(uint2*)(base + 128) = make_uint2(*(uint32_t*)&hy01, *(uint32_t*)&hy23);
        }
    }
    __syncthreads();

    uint32_t qfr[8][4];  // Q fragments, register-resident for the whole kernel
    {
        const uint32_t qa = sb + OFF_K0 + (w * 16 + (lane & 15)) * QSTR + (lane >> 4) * 16;
#pragma unroll
        for (int ks = 0; ks < 8; ++ks)
            LDSM4(qfr[ks][0], qfr[ks][1], qfr[ks][2], qfr[ks][3], qa + ks * 32);
    }
    __syncthreads();  // all warps done reading staging before K0 cp.async lands

    // ---- prologue B: fill the 4-group async pipeline: K0 | V0 | K1 | V1 ------
    load_K(kvs[0], 0);
    CPA_COMMIT();
    load_V(kvs[0], 0);
    CPA_COMMIT();
    if (ntl > 1) load_K(kvs[1], 1);
    CPA_COMMIT();
    if (ntl > 1) load_V(kvs[1], 1);
    CPA_COMMIT();

    const int brow = (lane & 7) + ((lane >> 4) << 3);
    const int qi = q0 + w * 16 + (lane >> 2);
    const int jc = 2 * (lane & 3);

    float o[16][4];
#pragma unroll
    for (int nt = 0; nt < 16; ++nt)
#pragma unroll
        for (int e = 0; e < 4; ++e) o[nt][e] = 0.f;
    u64 ls0v = 0ull, ls1v = 0ull;

    for (int t = 0; t < ntl; ++t) {
        const int kv0 = kvs[t];
        const int buf = t & 1;

        // K(t) done (3 newer groups may pend)
        CPA_WAIT3();
        __syncthreads();

        // ---- S = Q K^T (Q from registers) ----
        const uint32_t ka = sb + OFF_K0 + buf * K_SZ + brow * QSTR + (lane & 8) * 2;
        float sacc[8][4];
#pragma unroll
        for (int ct = 0; ct < 8; ++ct)
#pragma unroll
            for (int e = 0; e < 4; ++e) sacc[ct][e] = 0.f;
#pragma unroll
        for (int ks = 0; ks < 8; ++ks) {
#pragma unroll
            for (int np = 0; np < 4; ++np) {
                uint32_t kb[4];
                LDSM4(kb[0], kb[1], kb[2], kb[3], ka + np * (16 * QSTR) + ks * 32);
                MMA4(sacc[2 * np], qfr[ks], kb[0], kb[1]);
                MMA4(sacc[2 * np + 1], qfr[ks], kb[2], kb[3]);
            }
        }

        // all warps done reading K(t) -> prefetch K(t+2) into same buffer
        __syncthreads();
        if (t + 2 < ntl) load_K(kvs[t + 2], buf);
        CPA_COMMIT();

        // ---- softmax(t): p = 2^s (packed f32x2), mask only boundary tiles ----
        const bool full = (kv0 + BN <= q0 + 1) &&
                          ((kv0 >= q0 - WIN + BN - 1) || (kv0 + BN <= NMETA));
        uint32_t ph[4][4];
        if (full) {
#pragma unroll
            for (int ct = 0; ct < 8; ++ct) {
                u64 p01 = fexp2x2(pk2(sacc[ct][0], sacc[ct][1]));
                u64 p23 = fexp2x2(pk2(sacc[ct][2], sacc[ct][3]));
                ls0v = add2(ls0v, p01);
                ls1v = add2(ls1v, p23);
                float2 f01 = upk2(p01), f23 = upk2(p23);
                __half2 h01 = __floats2half2_rn(f01.x, f01.y);
                __half2 h23 = __floats2half2_rn(f23.x, f23.y);
                ph[ct >> 1][(ct & 1) * 2] = *(uint32_t*)&h01;
                ph[ct >> 1][(ct & 1) * 2 + 1] = *(uint32_t*)&h23;
            }
        } else {
#pragma unroll
            for (int ct = 0; ct < 8; ++ct) {
                int j0 = kv0 + ct * 8 + jc;
                float s[4];
#pragma unroll
                for (int e = 0; e < 4; ++e) {
                    int j = j0 + (e & 1);
                    int qr = qi + (e >> 1) * 8;
                    bool ok = (j <= qr) && ((qr - j) <= WIN || j < NMETA);
                    s[e] = ok ? sacc[ct][e] : -126.0f;
                }
                u64 p01 = fexp2x2(pk2(s[0], s[1]));
                u64 p23 = fexp2x2(pk2(s[2], s[3]));
                ls0v = add2(ls0v, p01);
                ls1v = add2(ls1v, p23);
                float2 f01 = upk2(p01), f23 = upk2(p23);
                __half2 h01 = __floats2half2_rn(f01.x, f01.y);
                __half2 h23 = __floats2half2_rn(f23.x, f23.y);
                ph[ct >> 1][(ct & 1) * 2] = *(uint32_t*)&h01;
                ph[ct >> 1][(ct & 1) * 2 + 1] = *(uint32_t*)&h23;
            }
        }

        // V(t) done (3 newer groups may pend)
        CPA_WAIT3();
        __syncthreads();

        // ---- O += P V ----
        const uint32_t va = sb + OFF_V0 + buf * V_SZ + brow * VSTR + (lane & 8) * 2;
#pragma unroll
        for (int kk = 0; kk < 4; ++kk) {
#pragma unroll
            for (int ntp = 0; ntp < 8; ++ntp) {
                uint32_t vb[4];
                LDSM4(vb[0], vb[1], vb[2], vb[3], va + ntp * (16 * VSTR) + kk * 32);
                MMA4(o[2 * ntp], ph[kk], vb[0], vb[1]);
                MMA4(o[2 * ntp + 1], ph[kk], vb[2], vb[3]);
            }
        }

        // all warps done reading V(t) -> prefetch V(t+2) into same buffer
        __syncthreads();
        if (t + 2 < ntl) load_V(kvs[t + 2], buf);
        CPA_COMMIT();
    }

    // ---- epilogue: quad row-sum reduce, normalize, store ----
    float2 l0 = upk2(ls0v), l1 = upk2(ls1v);
    float ls0 = l0.x + l0.y, ls1 = l1.x + l1.y;
    ls0 += __shfl_xor_sync(0xffffffffu, ls0, 1);
    ls0 += __shfl_xor_sync(0xffffffffu, ls0, 2);
    ls1 += __shfl_xor_sync(0xffffffffu, ls1, 1);
    ls1 += __shfl_xor_sync(0xffffffffu, ls1, 2);
    float inv0 = 1.0f / ls0, inv1 = 1.0f / ls1;
    float* ob0 = out + (size_t)qi * (NQH * HD) + h * HD + jc;
    float* ob1 = out + (size_t)(qi + 8) * (NQH * HD) + h * HD + jc;
#pragma unroll
    for (int nt = 0; nt < 16; ++nt) {
        *(float2*)(ob0 + nt * 8) = make_float2(o[nt][0] * inv0, o[nt][1] * inv0);
        *(float2*)(ob1 + nt * 8) = make_float2(o[nt][2] * inv1, o[nt][3] * inv1);
    }
}

extern "C" void kernel_launch(void* const* d_in, const int* in_sizes, int n_in,
                              void* d_out, int out_size) {
    const float* q = (const float*)d_in[0];
    const float* k = (const float*)d_in[1];
    const float* v = (const float*)d_in[2];
    float* out = (float*)d_out;

    prep_kernel<<<ROPE_BLOCKS + VT_BLOCKS, 256>>>(k, v);

    cudaFuncSetAttribute(attn_kernel, cudaFuncAttributeMaxDynamicSharedMemorySize, SMEM_TOTAL);
    attn_kernel<<<dim3(S_LEN / BM, NQH), 128, SMEM_TOTAL>>>(q, out);
}